// round 5
// baseline (speedup 1.0000x reference)
#include <cuda_runtime.h>

#define NPTS    4096
#define BATCH   4
#define TPB     256
#define TILE    256                    // square tile side (i and j extent per block)
#define T       (NPTS / TILE)          // 16
#define NSYM    (T * (T + 1) / 2)      // 136
#define NCROSS  (T * T)                // 256
#define BPB     (2 * NSYM + NCROSS)    // 528
#define NBLOCKS (BPB * BATCH)          // 2112

// sqrt(log2(e)): p = x*SCALE  =>  p_i.p_j = log2(e) * x_i.x_j
#define COORD_SCALE 1.2011224087864498f

__device__ float g_partials[NBLOCKS];
__device__ unsigned int g_count = 0;

typedef unsigned long long ull;

__device__ __forceinline__ ull pack2(float lo, float hi) {
    ull r;
    asm("mov.b64 %0, {%1, %2};" : "=l"(r) : "f"(lo), "f"(hi));
    return r;
}
__device__ __forceinline__ void unpack2(ull v, float& lo, float& hi) {
    asm("mov.b64 {%0, %1}, %2;" : "=f"(lo), "=f"(hi) : "l"(v));
}
__device__ __forceinline__ ull fma2(ull a, ull b, ull c) {
    ull d;
    asm("fma.rn.f32x2 %0, %1, %2, %3;" : "=l"(d) : "l"(a), "l"(b), "l"(c));
    return d;
}
__device__ __forceinline__ ull mul2(ull a, ull b) {
    ull d;
    asm("mul.rn.f32x2 %0, %1, %2;" : "=l"(d) : "l"(a), "l"(b));
    return d;
}
__device__ __forceinline__ float ex2(float x) {
    float r;
    asm("ex2.approx.ftz.f32 %0, %1;" : "=f"(r) : "f"(x));
    return r;
}

// j-tile layout: per j-pair (2 adjacent j's), 3 float4s:
//   [0] = {qx_e, qx_o, qy_e, qy_o}
//   [1] = {qz_e, qz_o, mx_e, mx_o}
//   [2] = {my_e, my_o, mz_e, mz_o}
// m = n_j * 2^{c_j} (exponent constants folded into normals)

__global__ void __launch_bounds__(TPB, 5)
varifold_fused(const float* __restrict__ xyz1,
               const float* __restrict__ xyz2,
               const float* __restrict__ nor1,
               const float* __restrict__ nor2,
               float* __restrict__ out)
{
    __shared__ __align__(16) float4 sb[(TILE / 2) * 3];
    __shared__ float warpsum[TPB / 32];

    const int tid = threadIdx.x;
    const int b   = blockIdx.y;

    // ---- decode block -> (term, ti, tj, weight) ----
    int idx = blockIdx.x;
    int term, ti, tj;
    float w;
    if (idx < 2 * NSYM) {
        term = (idx < NSYM) ? 0 : 1;
        int k = (idx < NSYM) ? idx : idx - NSYM;
        ti = 0;
        while (k >= T - ti) { k -= T - ti; ti++; }
        tj = ti + k;
        w = (ti == tj) ? 1.0f : 2.0f;   // symmetric: off-diag counted twice
    } else {
        term = 2;
        const int q = idx - 2 * NSYM;
        ti = q >> 4;                    // T == 16
        tj = q & (T - 1);
        w = -2.0f;
    }

    const float* xa; const float* xb; const float* na; const float* nb;
    if (term == 0)      { xa = xyz1; xb = xyz1; na = nor1; nb = nor1; }
    else if (term == 1) { xa = xyz2; xb = xyz2; na = nor2; nb = nor2; }
    else                { xa = xyz1; xb = xyz2; na = nor1; nb = nor2; }

    const long boff = (long)b * NPTS * 3;
    xa += boff; xb += boff; na += boff; nb += boff;

    // ---- fill j tile (exactly TILE points, one per thread) ----
    {
        const int j  = tj * TILE + tid;
        const float qx = xb[j * 3 + 0] * COORD_SCALE;
        const float qy = xb[j * 3 + 1] * COORD_SCALE;
        const float qz = xb[j * 3 + 2] * COORD_SCALE;
        const float sj = ex2(-0.5f * (qx * qx + qy * qy + qz * qz));
        const float mx = nb[j * 3 + 0] * sj;
        const float my = nb[j * 3 + 1] * sj;
        const float mz = nb[j * 3 + 2] * sj;
        const int jp = tid >> 1;
        const int l  = tid & 1;
        float* base = (float*)&sb[jp * 3];
        base[0 + l]  = qx;  base[2 + l]  = qy;
        base[4 + l]  = qz;  base[6 + l]  = mx;
        base[8 + l]  = my;  base[10 + l] = mz;
    }

    // ---- register-resident i point: p_i and n'_i = n_i * 2^{c_i} ----
    ull px, py, pz, nx, ny, nz, acc;
    {
        const int i = ti * TILE + tid;
        const float ax = xa[i * 3 + 0] * COORD_SCALE;
        const float ay = xa[i * 3 + 1] * COORD_SCALE;
        const float az = xa[i * 3 + 2] * COORD_SCALE;
        const float si = ex2(-0.5f * (ax * ax + ay * ay + az * az));
        const float bx = na[i * 3 + 0] * si;
        const float by = na[i * 3 + 1] * si;
        const float bz = na[i * 3 + 2] * si;
        px = pack2(ax, ax);
        py = pack2(ay, ay);
        pz = pack2(az, az);
        nx = pack2(bx, bx);
        ny = pack2(by, by);
        nz = pack2(bz, bz);
        acc = 0ull;
    }
    __syncthreads();

    // ---- main loop: 2 j-points per iteration via f32x2 ----
    const ulonglong2* jb = (const ulonglong2*)sb;
    #pragma unroll 4
    for (int jp = 0; jp < TILE / 2; jp++) {
        const ulonglong2 u0 = jb[jp * 3 + 0];   // qx2, qy2
        const ulonglong2 u1 = jb[jp * 3 + 1];   // qz2, mx2
        const ulonglong2 u2 = jb[jp * 3 + 2];   // my2, mz2
        // dot = p_i . p_j  (exponent; constants folded into normals)
        ull a = mul2(px, u0.x);
        a = fma2(py, u0.y, a);
        a = fma2(pz, u1.x, a);
        // D' = n'_i . n'_j
        ull d = mul2(nx, u1.y);
        d = fma2(ny, u2.x, d);
        d = fma2(nz, u2.y, d);
        // acc += (2^dot * D')^2 = exp(-S) * D^2
        float a0, a1;
        unpack2(a, a0, a1);
        const ull e  = pack2(ex2(a0), ex2(a1));
        const ull td = mul2(e, d);
        acc = fma2(td, td, acc);
    }

    // ---- block reduction (deterministic) ----
    float v;
    {
        float a0, a1;
        unpack2(acc, a0, a1);
        v = a0 + a1;
    }
    #pragma unroll
    for (int o = 16; o > 0; o >>= 1)
        v += __shfl_xor_sync(0xffffffffu, v, o);
    if ((tid & 31) == 0) warpsum[tid >> 5] = v;
    __syncthreads();

    __shared__ bool is_last;
    if (tid == 0) {
        float s = 0.0f;
        #pragma unroll
        for (int k = 0; k < TPB / 32; k++) s += warpsum[k];
        const int blin = blockIdx.y * gridDim.x + blockIdx.x;
        g_partials[blin] = s * w;
        __threadfence();
        const unsigned int done = atomicAdd(&g_count, 1u);
        is_last = (done == (unsigned int)(NBLOCKS - 1));
    }
    __syncthreads();

    // ---- last block finalizes (fixed order => deterministic) ----
    if (is_last) {
        float r = 0.0f;
        for (int i = tid; i < NBLOCKS; i += TPB)
            r += __ldcg(&g_partials[i]);
        #pragma unroll
        for (int o = 16; o > 0; o >>= 1)
            r += __shfl_xor_sync(0xffffffffu, r, o);
        if ((tid & 31) == 0) warpsum[tid >> 5] = r;
        __syncthreads();
        if (tid == 0) {
            float s = 0.0f;
            #pragma unroll
            for (int k = 0; k < TPB / 32; k++) s += warpsum[k];
            out[0] = s;
            g_count = 0;   // reset for next graph replay
        }
    }
}

extern "C" void kernel_launch(void* const* d_in, const int* in_sizes, int n_in,
                              void* d_out, int out_size)
{
    const float* xyz1 = (const float*)d_in[0];
    const float* xyz2 = (const float*)d_in[1];
    const float* nor1 = (const float*)d_in[2];
    const float* nor2 = (const float*)d_in[3];

    dim3 grid(BPB, BATCH);
    varifold_fused<<<grid, TPB>>>(xyz1, xyz2, nor1, nor2, (float*)d_out);
}

// round 6
// speedup vs baseline: 1.0322x; 1.0322x over previous
#include <cuda_runtime.h>

#define NPTS    4096
#define BATCH   4
#define TPB     256
#define ITILE   2
#define TILE    512                    // square tile side for pair decomposition
#define T       (NPTS / TILE)          // 8
#define JSUB    256                    // j extent per block (one smem fill)
#define JSPLIT  (TILE / JSUB)          // 2
#define NSYM    (T * (T + 1) / 2)      // 36
#define NCROSS  (T * T)                // 64
#define PAIRS   (2 * NSYM + NCROSS)    // 136 tile-pairs per batch
#define BPB     (PAIRS * JSPLIT)       // 272 blocks per batch
#define NBLOCKS (BPB * BATCH)          // 1088

// sqrt(log2(e)): p = x*SCALE  =>  p_i.p_j = log2(e) * x_i.x_j
#define COORD_SCALE 1.2011224087864498f

__device__ float g_partials[NBLOCKS];
__device__ unsigned int g_count = 0;

typedef unsigned long long ull;

__device__ __forceinline__ ull pack2(float lo, float hi) {
    ull r;
    asm("mov.b64 %0, {%1, %2};" : "=l"(r) : "f"(lo), "f"(hi));
    return r;
}
__device__ __forceinline__ void unpack2(ull v, float& lo, float& hi) {
    asm("mov.b64 {%0, %1}, %2;" : "=f"(lo), "=f"(hi) : "l"(v));
}
__device__ __forceinline__ ull fma2(ull a, ull b, ull c) {
    ull d;
    asm("fma.rn.f32x2 %0, %1, %2, %3;" : "=l"(d) : "l"(a), "l"(b), "l"(c));
    return d;
}
__device__ __forceinline__ ull mul2(ull a, ull b) {
    ull d;
    asm("mul.rn.f32x2 %0, %1, %2;" : "=l"(d) : "l"(a), "l"(b));
    return d;
}
__device__ __forceinline__ float ex2(float x) {
    float r;
    asm("ex2.approx.ftz.f32 %0, %1;" : "=f"(r) : "f"(x));
    return r;
}

// j-tile layout: per j-pair (2 adjacent j's), 3 float4s:
//   [0] = {qx_e, qx_o, qy_e, qy_o}
//   [1] = {qz_e, qz_o, mx_e, mx_o}
//   [2] = {my_e, my_o, mz_e, mz_o}
// m = n_j * 2^{c_j} (exponent constants folded into normals)

__global__ void __launch_bounds__(TPB, 4)
varifold_fused(const float* __restrict__ xyz1,
               const float* __restrict__ xyz2,
               const float* __restrict__ nor1,
               const float* __restrict__ nor2,
               float* __restrict__ out)
{
    __shared__ __align__(16) float4 sb[(JSUB / 2) * 3];
    __shared__ float warpsum[TPB / 32];

    const int tid = threadIdx.x;
    const int b   = blockIdx.y;

    // ---- decode block -> (term, ti, tj, jhalf, weight) ----
    const int jhalf = blockIdx.x & (JSPLIT - 1);
    int idx = blockIdx.x >> 1;         // tile-pair index 0..PAIRS-1
    int term, ti, tj;
    float w;
    if (idx < 2 * NSYM) {
        term = (idx < NSYM) ? 0 : 1;
        int k = (idx < NSYM) ? idx : idx - NSYM;
        ti = 0;
        while (k >= T - ti) { k -= T - ti; ti++; }
        tj = ti + k;
        w = (ti == tj) ? 1.0f : 2.0f;   // symmetric: off-diag counted twice
    } else {
        term = 2;
        const int q = idx - 2 * NSYM;
        ti = q >> 3;                    // T == 8
        tj = q & (T - 1);
        w = -2.0f;
    }

    const float* xa; const float* xb; const float* na; const float* nb;
    if (term == 0)      { xa = xyz1; xb = xyz1; na = nor1; nb = nor1; }
    else if (term == 1) { xa = xyz2; xb = xyz2; na = nor2; nb = nor2; }
    else                { xa = xyz1; xb = xyz2; na = nor1; nb = nor2; }

    const long boff = (long)b * NPTS * 3;
    xa += boff; xb += boff; na += boff; nb += boff;

    // ---- fill j tile (JSUB points, one per thread) ----
    {
        const int j  = tj * TILE + jhalf * JSUB + tid;
        const float qx = xb[j * 3 + 0] * COORD_SCALE;
        const float qy = xb[j * 3 + 1] * COORD_SCALE;
        const float qz = xb[j * 3 + 2] * COORD_SCALE;
        const float sj = ex2(-0.5f * (qx * qx + qy * qy + qz * qz));
        const float mx = nb[j * 3 + 0] * sj;
        const float my = nb[j * 3 + 1] * sj;
        const float mz = nb[j * 3 + 2] * sj;
        const int jp = tid >> 1;
        const int l  = tid & 1;
        float* base = (float*)&sb[jp * 3];
        base[0 + l]  = qx;  base[2 + l]  = qy;
        base[4 + l]  = qz;  base[6 + l]  = mx;
        base[8 + l]  = my;  base[10 + l] = mz;
    }

    // ---- register-resident i points: p_i and n'_i = n_i * 2^{c_i} ----
    ull px[ITILE], py[ITILE], pz[ITILE];
    ull nx[ITILE], ny[ITILE], nz[ITILE], acc[ITILE];
    #pragma unroll
    for (int t = 0; t < ITILE; t++) {
        const int i = ti * TILE + t * TPB + tid;
        const float ax = xa[i * 3 + 0] * COORD_SCALE;
        const float ay = xa[i * 3 + 1] * COORD_SCALE;
        const float az = xa[i * 3 + 2] * COORD_SCALE;
        const float si = ex2(-0.5f * (ax * ax + ay * ay + az * az));
        const float bx = na[i * 3 + 0] * si;
        const float by = na[i * 3 + 1] * si;
        const float bz = na[i * 3 + 2] * si;
        px[t] = pack2(ax, ax);
        py[t] = pack2(ay, ay);
        pz[t] = pack2(az, az);
        nx[t] = pack2(bx, bx);
        ny[t] = pack2(by, by);
        nz[t] = pack2(bz, bz);
        acc[t] = 0ull;
    }
    __syncthreads();

    // ---- main loop: 2 j-points x ITILE i-points per iteration ----
    const ulonglong2* jb = (const ulonglong2*)sb;
    #pragma unroll 2
    for (int jp = 0; jp < JSUB / 2; jp++) {
        const ulonglong2 u0 = jb[jp * 3 + 0];   // qx2, qy2
        const ulonglong2 u1 = jb[jp * 3 + 1];   // qz2, mx2
        const ulonglong2 u2 = jb[jp * 3 + 2];   // my2, mz2
        #pragma unroll
        for (int t = 0; t < ITILE; t++) {
            // dot = p_i . p_j  (exponent; constants folded into normals)
            ull a = mul2(px[t], u0.x);
            a = fma2(py[t], u0.y, a);
            a = fma2(pz[t], u1.x, a);
            // D' = n'_i . n'_j
            ull d = mul2(nx[t], u1.y);
            d = fma2(ny[t], u2.x, d);
            d = fma2(nz[t], u2.y, d);
            // acc += (2^dot * D')^2 = exp(-S) * D^2
            float a0, a1;
            unpack2(a, a0, a1);
            const ull e  = pack2(ex2(a0), ex2(a1));
            const ull td = mul2(e, d);
            acc[t] = fma2(td, td, acc[t]);
        }
    }

    // ---- block reduction (deterministic) ----
    float v = 0.0f;
    #pragma unroll
    for (int t = 0; t < ITILE; t++) {
        float a0, a1;
        unpack2(acc[t], a0, a1);
        v += a0 + a1;
    }
    #pragma unroll
    for (int o = 16; o > 0; o >>= 1)
        v += __shfl_xor_sync(0xffffffffu, v, o);
    if ((tid & 31) == 0) warpsum[tid >> 5] = v;
    __syncthreads();

    __shared__ bool is_last;
    if (tid == 0) {
        float s = 0.0f;
        #pragma unroll
        for (int k = 0; k < TPB / 32; k++) s += warpsum[k];
        const int blin = blockIdx.y * gridDim.x + blockIdx.x;
        g_partials[blin] = s * w;
        __threadfence();
        const unsigned int done = atomicAdd(&g_count, 1u);
        is_last = (done == (unsigned int)(NBLOCKS - 1));
    }
    __syncthreads();

    // ---- last block finalizes (fixed order => deterministic) ----
    if (is_last) {
        float r = 0.0f;
        for (int i = tid; i < NBLOCKS; i += TPB)
            r += __ldcg(&g_partials[i]);
        #pragma unroll
        for (int o = 16; o > 0; o >>= 1)
            r += __shfl_xor_sync(0xffffffffu, r, o);
        if ((tid & 31) == 0) warpsum[tid >> 5] = r;
        __syncthreads();
        if (tid == 0) {
            float s = 0.0f;
            #pragma unroll
            for (int k = 0; k < TPB / 32; k++) s += warpsum[k];
            out[0] = s;
            g_count = 0;   // reset for next graph replay
        }
    }
}

extern "C" void kernel_launch(void* const* d_in, const int* in_sizes, int n_in,
                              void* d_out, int out_size)
{
    const float* xyz1 = (const float*)d_in[0];
    const float* xyz2 = (const float*)d_in[1];
    const float* nor1 = (const float*)d_in[2];
    const float* nor2 = (const float*)d_in[3];

    dim3 grid(BPB, BATCH);
    varifold_fused<<<grid, TPB>>>(xyz1, xyz2, nor1, nor2, (float*)d_out);
}

// round 7
// speedup vs baseline: 1.1166x; 1.0818x over previous
#include <cuda_runtime.h>

#define NPTS    4096
#define BATCH   4
#define TPB     256
#define ITILE   2
#define TILE    512                    // square tile side
#define T       (NPTS / TILE)          // 8
#define JSUB    256                    // smem sub-tile width
#define NSYM    (T * (T + 1) / 2)      // 36
#define NCROSS  (T * T)                // 64
#define BPB     (2 * NSYM + NCROSS)    // 136
#define NBLOCKS (BPB * BATCH)          // 544

// sqrt(log2(e)): p = x*SCALE  =>  p_i.p_j = log2(e) * x_i.x_j
#define COORD_SCALE 1.2011224087864498f

__device__ float g_partials[NBLOCKS];
__device__ unsigned int g_count = 0;

typedef unsigned long long ull;

__device__ __forceinline__ ull pack2(float lo, float hi) {
    ull r;
    asm("mov.b64 %0, {%1, %2};" : "=l"(r) : "f"(lo), "f"(hi));
    return r;
}
__device__ __forceinline__ void unpack2(ull v, float& lo, float& hi) {
    asm("mov.b64 {%0, %1}, %2;" : "=f"(lo), "=f"(hi) : "l"(v));
}
__device__ __forceinline__ ull fma2(ull a, ull b, ull c) {
    ull d;
    asm("fma.rn.f32x2 %0, %1, %2, %3;" : "=l"(d) : "l"(a), "l"(b), "l"(c));
    return d;
}
__device__ __forceinline__ ull mul2(ull a, ull b) {
    ull d;
    asm("mul.rn.f32x2 %0, %1, %2;" : "=l"(d) : "l"(a), "l"(b));
    return d;
}
__device__ __forceinline__ float ex2(float x) {
    float r;
    asm("ex2.approx.ftz.f32 %0, %1;" : "=f"(r) : "f"(x));
    return r;
}

// j-tile layout: per j-pair (2 adjacent j's), 3 float4s:
//   [0] = {qx_e, qx_o, qy_e, qy_o}
//   [1] = {qz_e, qz_o, mx_e, mx_o}
//   [2] = {my_e, my_o, mz_e, mz_o}
// m = n_j * 2^{c_j} (exponent constants folded into normals)

__global__ void __launch_bounds__(TPB, 4)
varifold_fused(const float* __restrict__ xyz1,
               const float* __restrict__ xyz2,
               const float* __restrict__ nor1,
               const float* __restrict__ nor2,
               float* __restrict__ out)
{
    // +3 float4 padding so the software-pipeline prefetch past the end is safe
    __shared__ __align__(16) float4 sb[(JSUB / 2) * 3 + 3];
    __shared__ float warpsum[TPB / 32];

    const int tid = threadIdx.x;
    const int b   = blockIdx.y;

    // ---- decode block -> (term, ti, tj, weight) ----
    int idx = blockIdx.x;
    int term, ti, tj;
    float w;
    if (idx < 2 * NSYM) {
        term = (idx < NSYM) ? 0 : 1;
        int k = (idx < NSYM) ? idx : idx - NSYM;
        ti = 0;
        while (k >= T - ti) { k -= T - ti; ti++; }
        tj = ti + k;
        w = (ti == tj) ? 1.0f : 2.0f;   // symmetric: off-diag counted twice
    } else {
        term = 2;
        const int q = idx - 2 * NSYM;
        ti = q >> 3;                    // T == 8
        tj = q & (T - 1);
        w = -2.0f;
    }

    const float* xa; const float* xb; const float* na; const float* nb;
    if (term == 0)      { xa = xyz1; xb = xyz1; na = nor1; nb = nor1; }
    else if (term == 1) { xa = xyz2; xb = xyz2; na = nor2; nb = nor2; }
    else                { xa = xyz1; xb = xyz2; na = nor1; nb = nor2; }

    const long boff = (long)b * NPTS * 3;
    xa += boff; xb += boff; na += boff; nb += boff;

    // ---- register-resident i points: p_i and n'_i = n_i * 2^{c_i} ----
    ull px[ITILE], py[ITILE], pz[ITILE];
    ull nx[ITILE], ny[ITILE], nz[ITILE], acc[ITILE];
    #pragma unroll
    for (int t = 0; t < ITILE; t++) {
        const int i = ti * TILE + t * TPB + tid;
        const float ax = xa[i * 3 + 0] * COORD_SCALE;
        const float ay = xa[i * 3 + 1] * COORD_SCALE;
        const float az = xa[i * 3 + 2] * COORD_SCALE;
        const float si = ex2(-0.5f * (ax * ax + ay * ay + az * az));
        const float bx = na[i * 3 + 0] * si;
        const float by = na[i * 3 + 1] * si;
        const float bz = na[i * 3 + 2] * si;
        px[t] = pack2(ax, ax);
        py[t] = pack2(ay, ay);
        pz[t] = pack2(az, az);
        nx[t] = pack2(bx, bx);
        ny[t] = pack2(by, by);
        nz[t] = pack2(bz, bz);
        acc[t] = 0ull;
    }

    // ---- j loop over TILE in JSUB-wide smem sub-tiles ----
    for (int j0 = tj * TILE; j0 < tj * TILE + TILE; j0 += JSUB) {
        __syncthreads();
        {
            const int j  = j0 + tid;
            const float qx = xb[j * 3 + 0] * COORD_SCALE;
            const float qy = xb[j * 3 + 1] * COORD_SCALE;
            const float qz = xb[j * 3 + 2] * COORD_SCALE;
            const float sj = ex2(-0.5f * (qx * qx + qy * qy + qz * qz));
            const float mx = nb[j * 3 + 0] * sj;
            const float my = nb[j * 3 + 1] * sj;
            const float mz = nb[j * 3 + 2] * sj;
            const int jp = tid >> 1;
            const int l  = tid & 1;
            float* base = (float*)&sb[jp * 3];
            base[0 + l]  = qx;  base[2 + l]  = qy;
            base[4 + l]  = qz;  base[6 + l]  = mx;
            base[8 + l]  = my;  base[10 + l] = mz;
        }
        __syncthreads();

        const ulonglong2* jb = (const ulonglong2*)sb;
        // software pipeline: current j-pair regs (c*), prefetch next (n*)
        ulonglong2 c0 = jb[0], c1 = jb[1], c2 = jb[2];
        #pragma unroll 4
        for (int jp = 0; jp < JSUB / 2; jp++) {
            const ulonglong2 n0 = jb[(jp + 1) * 3 + 0];   // pads make last read safe
            const ulonglong2 n1 = jb[(jp + 1) * 3 + 1];
            const ulonglong2 n2 = jb[(jp + 1) * 3 + 2];

            // a-dots (both i chains)
            ull a0 = mul2(px[0], c0.x);
            ull a1 = mul2(px[1], c0.x);
            a0 = fma2(py[0], c0.y, a0);
            a1 = fma2(py[1], c0.y, a1);
            a0 = fma2(pz[0], c1.x, a0);
            a1 = fma2(pz[1], c1.x, a1);

            // issue all 4 EX2 back-to-back
            float a00, a01, a10, a11;
            unpack2(a0, a00, a01);
            unpack2(a1, a10, a11);
            const float e00 = ex2(a00);
            const float e01 = ex2(a01);
            const float e10 = ex2(a10);
            const float e11 = ex2(a11);

            // d-dots — independent work covering MUFU latency
            ull d0 = mul2(nx[0], c1.y);
            ull d1 = mul2(nx[1], c1.y);
            d0 = fma2(ny[0], c2.x, d0);
            d1 = fma2(ny[1], c2.x, d1);
            d0 = fma2(nz[0], c2.y, d0);
            d1 = fma2(nz[1], c2.y, d1);

            // combine: acc += (2^a * D')^2
            const ull e0 = pack2(e00, e01);
            const ull e1 = pack2(e10, e11);
            const ull t0 = mul2(e0, d0);
            const ull t1 = mul2(e1, d1);
            acc[0] = fma2(t0, t0, acc[0]);
            acc[1] = fma2(t1, t1, acc[1]);

            c0 = n0; c1 = n1; c2 = n2;
        }
    }

    // ---- block reduction (deterministic) ----
    float v = 0.0f;
    #pragma unroll
    for (int t = 0; t < ITILE; t++) {
        float a0, a1;
        unpack2(acc[t], a0, a1);
        v += a0 + a1;
    }
    #pragma unroll
    for (int o = 16; o > 0; o >>= 1)
        v += __shfl_xor_sync(0xffffffffu, v, o);
    if ((tid & 31) == 0) warpsum[tid >> 5] = v;
    __syncthreads();

    __shared__ bool is_last;
    if (tid == 0) {
        float s = 0.0f;
        #pragma unroll
        for (int k = 0; k < TPB / 32; k++) s += warpsum[k];
        const int blin = blockIdx.y * gridDim.x + blockIdx.x;
        g_partials[blin] = s * w;
        __threadfence();
        const unsigned int done = atomicAdd(&g_count, 1u);
        is_last = (done == (unsigned int)(NBLOCKS - 1));
    }
    __syncthreads();

    // ---- last block finalizes (fixed order => deterministic) ----
    if (is_last) {
        float r = 0.0f;
        for (int i = tid; i < NBLOCKS; i += TPB)
            r += __ldcg(&g_partials[i]);
        #pragma unroll
        for (int o = 16; o > 0; o >>= 1)
            r += __shfl_xor_sync(0xffffffffu, r, o);
        if ((tid & 31) == 0) warpsum[tid >> 5] = r;
        __syncthreads();
        if (tid == 0) {
            float s = 0.0f;
            #pragma unroll
            for (int k = 0; k < TPB / 32; k++) s += warpsum[k];
            out[0] = s;
            g_count = 0;   // reset for next graph replay
        }
    }
}

extern "C" void kernel_launch(void* const* d_in, const int* in_sizes, int n_in,
                              void* d_out, int out_size)
{
    const float* xyz1 = (const float*)d_in[0];
    const float* xyz2 = (const float*)d_in[1];
    const float* nor1 = (const float*)d_in[2];
    const float* nor2 = (const float*)d_in[3];

    dim3 grid(BPB, BATCH);
    varifold_fused<<<grid, TPB>>>(xyz1, xyz2, nor1, nor2, (float*)d_out);
}